// round 17
// baseline (speedup 1.0000x reference)
#include <cuda_runtime.h>
#include <cstdint>

// TSK fuzzy system via mma.sync tf32 tensor ops (baseline sm_80+ ISA).
// out[n] = sum_r fg_bar[n,r]*(x[n]·W[r]+b[r]); fg_bar separable-normalized.
// Pipeline: prep (memberships + W-fragment table + dup-bias table) ->
// main (FG gen in regs; ONE HMMA per k-tile for W cols 0-7; bias dot via
// packed f32x2 FMA on the same fg registers) -> finalize (fused reduce+out).

#define NSAMP 1024
#define NGROUP 128   // rule groups of 512
#define TILES 8      // sample tiles of 128

typedef unsigned long long ull;

__device__ float g_mg[NSAMP * 32];               // normalized memberships
__device__ uint2 g_B0[NGROUP * 2048];            // [g][kt*32+lane] W fragment
__device__ ulonglong2 g_bb[NGROUP * 256];        // [g][kt*4+j7] = {dup b[k0], dup b[k0+4]}
__device__ float g_part[NGROUP * 9 * NSAMP];     // [g][k][n]

__device__ __forceinline__ uint32_t tf32r(float f) {
    uint32_t r; asm("cvt.rna.tf32.f32 %0, %1;" : "=r"(r) : "f"(f)); return r;
}
__device__ __forceinline__ ull pack2(float f) {
    ull r; asm("mov.b64 %0, {%1, %1};" : "=l"(r) : "f"(f)); return r;
}
__device__ __forceinline__ ull pack2f(float a, float b) {
    ull r; asm("mov.b64 %0, {%1, %2};" : "=l"(r) : "f"(a), "f"(b)); return r;
}
__device__ __forceinline__ ull mul2(ull a, ull b) {
    ull d; asm("mul.rn.f32x2 %0, %1, %2;" : "=l"(d) : "l"(a), "l"(b)); return d;
}
__device__ __forceinline__ void fma2(ull& d, ull a, ull b) {
    asm("fma.rn.f32x2 %0, %1, %2, %0;" : "+l"(d) : "l"(a), "l"(b));
}
__device__ __forceinline__ void unpack2u(ull v, uint32_t& a, uint32_t& b) {
    asm("mov.b64 {%0, %1}, %2;" : "=r"(a), "=r"(b) : "l"(v));
}
__device__ __forceinline__ void unpack2f(ull v, float& a, float& b) {
    asm("mov.b64 {%0, %1}, %2;" : "=f"(a), "=f"(b) : "l"(v));
}
__device__ __forceinline__ void mma8(float* d, uint32_t a0, uint32_t a1,
                                     uint32_t a2, uint32_t a3,
                                     uint32_t b0, uint32_t b1) {
    asm volatile(
        "mma.sync.aligned.m16n8k8.row.col.f32.tf32.tf32.f32 "
        "{%0,%1,%2,%3}, {%4,%5,%6,%7}, {%8,%9}, {%0,%1,%2,%3};"
        : "+f"(d[0]), "+f"(d[1]), "+f"(d[2]), "+f"(d[3])
        : "r"(a0), "r"(a1), "r"(a2), "r"(a3), "r"(b0), "r"(b1));
}

// ---- prep: CTAs 0-7 = memberships; CTAs 8-135 = W fragments + bias table ----
__global__ __launch_bounds__(256) void prep_kernel(
    const float* __restrict__ x, const float* __restrict__ center,
    const float* __restrict__ sigma, const float* __restrict__ W,
    const float* __restrict__ b)
{
    int tid = threadIdx.x;
    if (blockIdx.x < 8) {
        int s = blockIdx.x * 128 + (tid & 127);
        int mh = tid >> 7;
        float4 xv4 = *reinterpret_cast<const float4*>(x + s * 8 + mh * 4);
        float xv[4] = {xv4.x, xv4.y, xv4.z, xv4.w};
#pragma unroll
        for (int mm = 0; mm < 4; mm++) {
            int m = mh * 4 + mm;
            float e[4], sum = 0.f;
#pragma unroll
            for (int j = 0; j < 4; j++) {
                float d = xv[mm] - center[m * 4 + j];
                float sg = sigma[m * 4 + j];
                e[j] = __expf(-0.5f * d * d * sg * sg);
                sum += e[j];
            }
            float inv = 1.0f / sum;
            float4 o = make_float4(e[0] * inv, e[1] * inv, e[2] * inv, e[3] * inv);
            *reinterpret_cast<float4*>(&g_mg[s * 32 + m * 4]) = o;
        }
    } else {
        // W fragments: g_B0[gy*2048 + kt*32 + l] = {tf32 W[k0][n0], tf32 W[k0+4][n0]},
        // k0 = kt*8+(l&3), n0 = l>>2 (0..7).  Bias: g_bb[gy*256 + kt*4 + j7].
        __shared__ float ws[512 * 9];
        int gy = blockIdx.x - 8;
        const float4* Wg4 = reinterpret_cast<const float4*>(W + (size_t)gy * 4096);
#pragma unroll
        for (int i = 0; i < 4; i++) {
            int fi = tid + i * 256;
            float4 v = Wg4[fi];
            int r = fi >> 1, h = fi & 1;
            float* row = ws + r * 9 + h * 4;
            row[0] = v.x; row[1] = v.y; row[2] = v.z; row[3] = v.w;
        }
        {
            float2 bv = reinterpret_cast<const float2*>(b + (size_t)gy * 512)[tid];
            ws[(2 * tid) * 9 + 8] = bv.x;
            ws[(2 * tid + 1) * 9 + 8] = bv.y;
        }
        __syncthreads();
#pragma unroll
        for (int e = 0; e < 8; e++) {
            int idx = tid + e * 256;
            int kt = idx >> 5, l = idx & 31;
            int n0 = l >> 2, k0 = kt * 8 + (l & 3);
            g_B0[gy * 2048 + idx] =
                make_uint2(tf32r(ws[k0 * 9 + n0]), tf32r(ws[(k0 + 4) * 9 + n0]));
        }
        {
            int kt = tid >> 2, j7 = tid & 3;
            int k0 = kt * 8 + j7;
            ulonglong2 o;
            o.x = pack2(ws[k0 * 9 + 8]);
            o.y = pack2(ws[(k0 + 4) * 9 + 8]);
            g_bb[gy * 256 + tid] = o;
        }
    }
}

// ---- main: 256 thr = 8 warps, warp owns one 16-row m-tile ----
__global__ __launch_bounds__(256) void tsk_kernel()
{
    __shared__ float s_mg[128 * 36];

    int tid = threadIdx.x, lane = tid & 31, w = tid >> 5;
    int gy = blockIdx.y, tile = blockIdx.x;

    // prologue: coalesced copy of this tile's memberships into padded smem
    {
        const float4* src = reinterpret_cast<const float4*>(g_mg + tile * 128 * 32);
#pragma unroll
        for (int i = 0; i < 4; i++) {
            int fi = tid + i * 256;
            float4 v = src[fi];
            int s = fi >> 3, c4 = fi & 7;
            *reinterpret_cast<float4*>(&s_mg[s * 36 + c4 * 4]) = v;
        }
    }
    __syncthreads();

    int srow = lane >> 2, j7 = lane & 3;
    const float* r0 = s_mg + (w * 16 + srow) * 36;
    const float* r1 = r0 + 8 * 36;

    int j0 = (gy >> 5) & 3, j1 = (gy >> 3) & 3, j2 = (gy >> 1) & 3;
    float pA = r0[j0] * r0[4 + j1] * r0[8 + j2] * r0[28 + j7];
    float pB = r1[j0] * r1[4 + j1] * r1[8 + j2] * r1[28 + j7];
    ull pre = pack2f(pA, pB);

    int j3b = (gy & 1) << 1;
    ull pm3[2], pm4[4], pm5[4], pm6[4];
#pragma unroll
    for (int t = 0; t < 2; t++) pm3[t] = pack2f(r0[12 + j3b + t], r1[12 + j3b + t]);
#pragma unroll
    for (int j = 0; j < 4; j++) {
        pm4[j] = pack2f(r0[16 + j], r1[16 + j]);
        pm5[j] = pack2f(r0[20 + j], r1[20 + j]);
        pm6[j] = pack2f(r0[24 + j], r1[24 + j]);
    }

    float d00[4] = {0, 0, 0, 0};
    ull cacc0 = 0ull, cacc1 = 0ull;   // packed {sample srow, srow+8} bias dots

    const uint2* Bp = g_B0 + gy * 2048 + lane;
    const ulonglong2* bbp = g_bb + gy * 256 + j7;

    // mainloop: 64 k-tiles; per kt: LDG.64 + LDG.128 + 2 mul2 + 2 fma2 + 1 HMMA
#pragma unroll 1
    for (int t3 = 0; t3 < 2; t3++) {
        ull b3 = mul2(pre, pm3[t3]);
#pragma unroll
        for (int t4 = 0; t4 < 4; t4++) {
            ull b4 = mul2(b3, pm4[t4]);
            int kt0 = t3 * 32 + t4 * 8;
#pragma unroll
            for (int t5 = 0; t5 < 4; t5++) {
                ull b5 = mul2(b4, pm5[t5]);
#pragma unroll
                for (int t6 = 0; t6 < 2; t6++) {
                    int kt = kt0 + t5 * 2 + t6;
                    uint2 bf = Bp[kt * 32];
                    ulonglong2 bb = bbp[kt * 4];
                    ull alo = mul2(b5, pm6[2 * t6]);       // rules kt*8+j7
                    ull ahi = mul2(b5, pm6[2 * t6 + 1]);   // rules kt*8+j7+4
                    uint32_t a0, a1, a2, a3;
                    unpack2u(alo, a0, a1);
                    unpack2u(ahi, a2, a3);
                    mma8(d00, a0, a1, a2, a3, bf.x, bf.y);
                    fma2(cacc0, alo, bb.x);
                    fma2(cacc1, ahi, bb.y);
                }
            }
        }
    }

    // bias: combine, reduce over j7 lanes (deterministic shfl), write k=8
    float cA, cB, cA1, cB1;
    unpack2f(cacc0, cA, cB);
    unpack2f(cacc1, cA1, cB1);
    cA += cA1; cB += cB1;
    cA += __shfl_xor_sync(0xFFFFFFFFu, cA, 1);
    cA += __shfl_xor_sync(0xFFFFFFFFu, cA, 2);
    cB += __shfl_xor_sync(0xFFFFFFFFu, cB, 1);
    cB += __shfl_xor_sync(0xFFFFFFFFu, cB, 2);

    {
        int k0 = j7 * 2;
        int n0 = tile * 128 + w * 16 + srow;
        float* gp = g_part + (size_t)gy * 9 * NSAMP;
        gp[(k0 + 0) * NSAMP + n0]     = d00[0];
        gp[(k0 + 1) * NSAMP + n0]     = d00[1];
        gp[(k0 + 0) * NSAMP + n0 + 8] = d00[2];
        gp[(k0 + 1) * NSAMP + n0 + 8] = d00[3];
        if (j7 == 0) {
            gp[8 * NSAMP + n0]     = cA;
            gp[8 * NSAMP + n0 + 8] = cB;
        }
    }
}

// ---- finalize: out[n] = sum_g (x[n]·A_g[:,n] + c_g[n]) ----
// 32 CTAs x 256: warp w sums groups [w*16, w*16+16), lane = sample in block.
__global__ __launch_bounds__(256) void finalize_kernel(
    const float* __restrict__ x, float* __restrict__ out)
{
    __shared__ float sm[8][32];
    int lane = threadIdx.x & 31, w = threadIdx.x >> 5;
    int n = blockIdx.x * 32 + lane;

    float xv[8];
    {
        float4 x0 = *reinterpret_cast<const float4*>(x + n * 8);
        float4 x1 = *reinterpret_cast<const float4*>(x + n * 8 + 4);
        xv[0] = x0.x; xv[1] = x0.y; xv[2] = x0.z; xv[3] = x0.w;
        xv[4] = x1.x; xv[5] = x1.y; xv[6] = x1.z; xv[7] = x1.w;
    }

    const int stride = 9 * NSAMP;
    const float* p = g_part + (size_t)w * 16 * stride + n;
    float o = 0.f;
#pragma unroll 4
    for (int g = 0; g < 16; g++) {
        const float* q = p + g * stride;
        float t = q[8 * NSAMP];
#pragma unroll
        for (int k = 0; k < 8; k++) t = fmaf(xv[k], q[k * NSAMP], t);
        o += t;
    }
    sm[w][lane] = o;
    __syncthreads();
    if (w == 0) {
        float t = ((sm[0][lane] + sm[1][lane]) + (sm[2][lane] + sm[3][lane]))
                + ((sm[4][lane] + sm[5][lane]) + (sm[6][lane] + sm[7][lane]));
        out[n] = t;
    }
}

extern "C" void kernel_launch(void* const* d_in, const int* in_sizes, int n_in,
                              void* d_out, int out_size) {
    const float* x      = (const float*)d_in[0];
    const float* center = (const float*)d_in[1];
    const float* sigma  = (const float*)d_in[2];
    const float* W      = (const float*)d_in[3];
    const float* b      = (const float*)d_in[4];
    float* out = (float*)d_out;

    prep_kernel<<<8 + NGROUP, 256>>>(x, center, sigma, W, b);
    dim3 grid(TILES, NGROUP);
    tsk_kernel<<<grid, 256>>>();
    finalize_kernel<<<NSAMP / 32, 256>>>(x, out);
}